// round 1
// baseline (speedup 1.0000x reference)
#include <cuda_runtime.h>
#include <cstdint>
#include <cstddef>

// ---------------------------------------------------------------------------
// Net_3813930959289: triplane bilinear gather (3 planes, 32ch, 512x512)
//                    + MLP 32->128->128->128->1 (ReLU), fp32 throughout.
//
// Strategy:
//  1) transpose planes [3,32,512,512] -> channel-last [3,512,512,32] in a
//     __device__ scratch so each texel's 32 channels are one 128B line.
//  2) transpose MLP weights to [k][j] layout in __device__ scratch.
//  3) fused kernel: 1 block (256 thr) per 128-point tile.
//     - warp-cooperative gather (8 lanes x float4 per texel)
//     - MLP layers as register-blocked packed-f32x2 GEMM with weights staged
//       to shared memory per layer.
// ---------------------------------------------------------------------------

#define RES   512
#define EMB   32
#define HID   128
#define TILE  128
#define NTHR  256

// 3*512*512*32 floats = 96 MB scratch (static device global: allowed)
__device__ __align__(16) float g_planesT[3 * RES * RES * EMB];
__device__ __align__(16) float g_wT0[EMB * HID];    // [k][j]
__device__ __align__(16) float g_wT1[HID * HID];
__device__ __align__(16) float g_wT2[HID * HID];

// ---------------- packed f32x2 helpers -------------------------------------
typedef unsigned long long u64;

__device__ __forceinline__ u64 fma2(u64 a, u64 b, u64 c) {
    u64 d;
    asm("fma.rn.f32x2 %0, %1, %2, %3;" : "=l"(d) : "l"(a), "l"(b), "l"(c));
    return d;
}
__device__ __forceinline__ u64 dup2(float a) {
    u64 d;
    asm("mov.b64 %0, {%1, %1};" : "=l"(d) : "f"(a));
    return d;
}
__device__ __forceinline__ u64 pack2f(float x, float y) {
    u64 d;
    asm("mov.b64 %0, {%1, %2};" : "=l"(d) : "f"(x), "f"(y));
    return d;
}
__device__ __forceinline__ float2 unpack2(u64 a) {
    float2 r;
    asm("mov.b64 {%0, %1}, %2;" : "=f"(r.x), "=f"(r.y) : "l"(a));
    return r;
}

// ---------------- transpose kernels ----------------------------------------
// planes [p][c][y][x] -> g_planesT [p][y][x][c]; 32c x 32x tiles via smem.
__global__ void transpose_planes_kernel(const float* __restrict__ planes) {
    __shared__ float s[32][33];
    int b  = blockIdx.x;               // 3 * 512 * 16 blocks
    int xb = b & 15;
    int y  = (b >> 4) & 511;
    int p  = b >> 13;
    int t  = threadIdx.x;
#pragma unroll
    for (int r = 0; r < 4; r++) {
        int e = t + r * 256;
        int c = e >> 5;
        int x = e & 31;
        size_t src = ((((size_t)p * 32 + c) * RES + y) << 9) + (xb << 5) + x;
        s[c][x] = planes[src];
    }
    __syncthreads();
#pragma unroll
    for (int r = 0; r < 4; r++) {
        int e = t + r * 256;
        int x = e >> 5;
        int c = e & 31;
        size_t dst = (((size_t)p * RES + y) * RES + (xb << 5) + x) * EMB + c;
        g_planesT[dst] = s[c][x];
    }
}

// weights [j][k] -> [k][j]
__global__ void transpose_weights_kernel(const float* __restrict__ w0,
                                         const float* __restrict__ w1,
                                         const float* __restrict__ w2) {
    int i = blockIdx.x * 256 + threadIdx.x;   // grid covers 16384
    if (i < EMB * HID) {
        int k = i >> 7, j = i & 127;
        g_wT0[i] = w0[j * EMB + k];
    }
    if (i < HID * HID) {
        int k = i >> 7, j = i & 127;
        g_wT1[i] = w1[j * HID + k];
        g_wT2[i] = w2[j * HID + k];
    }
}

// ---------------- fused gather + MLP ---------------------------------------
// smem layout (floats):
//   feats : [128][36]           ->  4608   @ 0
//   hA    : [128][128]          -> 16384   @ 4608
//   hB    : [128][128]          -> 16384   @ 20992
//   wbuf  : [128][128]          -> 16384   @ 37376
//   mi    : int  [3][128]       ->   384   @ 53760
//   mw    : float2 [3][128]     ->   768   @ 54144
// total 54912 floats = 219648 bytes
#define SMEM_FLOATS 54912
#define OFF_FEATS 0
#define OFF_HA    4608
#define OFF_HB    20992
#define OFF_WBUF  37376
#define OFF_MI    53760
#define OFF_MW    54144

__device__ __forceinline__ void stage_w(float* __restrict__ wbuf,
                                        const float* __restrict__ src,
                                        int n, int t) {
    const float4* s4 = (const float4*)src;
    float4* d4 = (float4*)wbuf;
    for (int i = t; i < (n >> 2); i += NTHR) d4[i] = __ldg(s4 + i);
}

// One layer: out[j][pt] = relu(bias[j] + sum_k in[k]*wT[k][j])
// Each thread: 2 points (ptA = t&63, ptB = ptA+64), 32 j's (16 f32x2 pairs).
// inAct addressed as inAct[k*sk + pt*sp].
__device__ __forceinline__ void mlp_layer(const float* __restrict__ inAct,
                                          float* __restrict__ outAct,
                                          const float* __restrict__ wbuf,
                                          const float* __restrict__ bias,
                                          int K, int sk, int sp, int t) {
    int ptA = t & 63;
    int ptB = ptA + 64;
    int j0  = (t >> 6) << 5;   // 0,32,64,96

    u64 acc0[16], acc1[16];
#pragma unroll
    for (int i = 0; i < 16; i++) {
        float bx = __ldg(bias + j0 + 2 * i);
        float by = __ldg(bias + j0 + 2 * i + 1);
        u64 bb = pack2f(bx, by);
        acc0[i] = bb;
        acc1[i] = bb;
    }

#pragma unroll 4
    for (int k = 0; k < K; k++) {
        float aA = inAct[k * sk + ptA * sp];
        float aB = inAct[k * sk + ptB * sp];
        u64 dA = dup2(aA);
        u64 dB = dup2(aB);
        const ulonglong2* wp = (const ulonglong2*)(wbuf + (k << 7) + j0);
#pragma unroll
        for (int i = 0; i < 8; i++) {
            ulonglong2 wv = wp[i];
            acc0[2 * i]     = fma2(wv.x, dA, acc0[2 * i]);
            acc0[2 * i + 1] = fma2(wv.y, dA, acc0[2 * i + 1]);
            acc1[2 * i]     = fma2(wv.x, dB, acc1[2 * i]);
            acc1[2 * i + 1] = fma2(wv.y, dB, acc1[2 * i + 1]);
        }
    }

#pragma unroll
    for (int i = 0; i < 16; i++) {
        float2 vA = unpack2(acc0[i]);
        float2 vB = unpack2(acc1[i]);
        vA.x = fmaxf(vA.x, 0.0f); vA.y = fmaxf(vA.y, 0.0f);
        vB.x = fmaxf(vB.x, 0.0f); vB.y = fmaxf(vB.y, 0.0f);
        int j = j0 + 2 * i;
        outAct[j * 128 + ptA]       = vA.x;
        outAct[j * 128 + ptB]       = vB.x;
        outAct[(j + 1) * 128 + ptA] = vA.y;
        outAct[(j + 1) * 128 + ptB] = vB.y;
    }
}

__global__ void __launch_bounds__(NTHR, 1)
fused_kernel(const float* __restrict__ coords,
             const float* __restrict__ b0,
             const float* __restrict__ b1,
             const float* __restrict__ b2,
             const float* __restrict__ w3,
             const float* __restrict__ b3,
             float* __restrict__ out, int N) {
    extern __shared__ float sm[];
    float*  feats = sm + OFF_FEATS;
    float*  hA    = sm + OFF_HA;
    float*  hB    = sm + OFF_HB;
    float*  wbuf  = sm + OFF_WBUF;
    int*    mi    = (int*)(sm + OFF_MI);
    float2* mw    = (float2*)(sm + OFF_MW);

    int t    = threadIdx.x;
    int base = blockIdx.x * TILE;

    // ---- Phase A: per-point coords -> (ix0, iy0, wx1, wy1) per plane ----
    if (t < TILE) {
        int g = base + t;
        bool ok = g < N;
        float cx = 0.f, cy = 0.f, cz = 0.f;
        if (ok) {
            cx = coords[3 * g + 0];
            cy = coords[3 * g + 1];
            cz = coords[3 * g + 2];
        }
#pragma unroll
        for (int p = 0; p < 3; p++) {
            float sx = (p == 0) ? cx : ((p == 1) ? cy : cx);
            float sy = (p == 0) ? cy : ((p == 1) ? cz : cz);
            int ix0, iy0; float wx1, wy1;
            if (ok) {
                float x = (sx + 1.0f) * 0.5f * (float)(RES - 1);
                float y = (sy + 1.0f) * 0.5f * (float)(RES - 1);
                float fx = floorf(x), fy = floorf(y);
                ix0 = (int)fx; iy0 = (int)fy;
                wx1 = x - fx;  wy1 = y - fy;
            } else {
                ix0 = 1000; iy0 = 1000; wx1 = 0.f; wy1 = 0.f;
            }
            mi[p * 128 + t] = (iy0 << 16) | (ix0 & 0xFFFF);
            mw[p * 128 + t] = make_float2(wx1, wy1);
        }
    }
    __syncthreads();

    // ---- Phase B: cooperative gather. 8 lanes per texel (4 texels/instr) ----
    {
        int w    = t >> 5;
        int lane = t & 31;
        int g4   = lane >> 3;   // group within warp (4 points in flight)
        int sub  = lane & 7;    // float4 slot within 128B texel line
#pragma unroll
        for (int r = 0; r < 4; r++) {
            int pt = w * 16 + r * 4 + g4;
            float4 acc = make_float4(0.f, 0.f, 0.f, 0.f);
#pragma unroll
            for (int p = 0; p < 3; p++) {
                int m = mi[p * 128 + pt];
                int ix0 = (int)(short)(m & 0xFFFF);
                int iy0 = m >> 16;
                float2 wf = mw[p * 128 + pt];
                float wx1 = wf.x, wy1 = wf.y;
                float wx0 = 1.0f - wx1, wy0 = 1.0f - wy1;
#pragma unroll
                for (int c = 0; c < 4; c++) {
                    int ix = ix0 + (c & 1);
                    int iy = iy0 + (c >> 1);
                    float wgt = ((c & 1) ? wx1 : wx0) * ((c >> 1) ? wy1 : wy0);
                    if ((unsigned)ix < (unsigned)RES && (unsigned)iy < (unsigned)RES) {
                        const float4* ptr =
                            (const float4*)(g_planesT +
                                ((((size_t)p * RES + iy) * RES + ix) << 5)) + sub;
                        float4 v = __ldg(ptr);
                        acc.x = fmaf(wgt, v.x, acc.x);
                        acc.y = fmaf(wgt, v.y, acc.y);
                        acc.z = fmaf(wgt, v.z, acc.z);
                        acc.w = fmaf(wgt, v.w, acc.w);
                    }
                }
            }
            *(float4*)(feats + pt * 36 + sub * 4) = acc;
        }
    }

    // ---- MLP ----
    stage_w(wbuf, g_wT0, EMB * HID, t);
    __syncthreads();
    mlp_layer(feats, hA, wbuf, b0, EMB, 1, 36, t);
    __syncthreads();

    stage_w(wbuf, g_wT1, HID * HID, t);
    __syncthreads();
    mlp_layer(hA, hB, wbuf, b1, HID, 128, 1, t);
    __syncthreads();

    stage_w(wbuf, g_wT2, HID * HID, t);
    __syncthreads();
    mlp_layer(hB, hA, wbuf, b2, HID, 128, 1, t);
    __syncthreads();

    // ---- output layer: out[pt] = b3 + sum_k hA[k][pt] * w3[k] ----
    if (t < TILE) {
        int g = base + t;
        float acc = __ldg(b3);
#pragma unroll 8
        for (int k = 0; k < HID; k++)
            acc = fmaf(hA[k * 128 + t], __ldg(w3 + k), acc);
        if (g < N) out[g] = acc;
    }
}

// ---------------------------------------------------------------------------
extern "C" void kernel_launch(void* const* d_in, const int* in_sizes, int n_in,
                              void* d_out, int out_size) {
    const float* coords = (const float*)d_in[0];
    const float* planes = (const float*)d_in[1];
    const float* w0     = (const float*)d_in[2];
    const float* b0     = (const float*)d_in[3];
    const float* w1     = (const float*)d_in[4];
    const float* b1     = (const float*)d_in[5];
    const float* w2     = (const float*)d_in[6];
    const float* b2     = (const float*)d_in[7];
    const float* w3     = (const float*)d_in[8];
    const float* b3     = (const float*)d_in[9];
    float* out = (float*)d_out;

    int N = in_sizes[0] / 3;

    static const int smem_bytes = SMEM_FLOATS * 4;
    cudaFuncSetAttribute(fused_kernel,
                         cudaFuncAttributeMaxDynamicSharedMemorySize,
                         smem_bytes);

    transpose_planes_kernel<<<3 * RES * (RES / 32), 256>>>(planes);
    transpose_weights_kernel<<<(HID * HID + 255) / 256, 256>>>(w0, w1, w2);

    int blocks = (N + TILE - 1) / TILE;
    fused_kernel<<<blocks, NTHR, smem_bytes>>>(coords, b0, b1, b2, w3, b3,
                                               out, N);
}

// round 2
// speedup vs baseline: 1.1783x; 1.1783x over previous
#include <cuda_runtime.h>
#include <cstdint>
#include <cstddef>

// ---------------------------------------------------------------------------
// Net_3813930959289: triplane bilinear gather (3 planes, 32ch, 512x512)
//                    + MLP 32->128->128->128->1 (ReLU), fp32 throughout.
//
// Round 2: persistent blocks with ALL weights resident in shared memory.
//  - transpose planes to channel-last once (separate kernel)
//  - fused kernel: grid=456 blocks, each loops over 64-point tiles.
//    Weights w0/w1/w2 transposed into smem ONCE per block; biases + w3 too.
//    Per tile: cooperative gather + 3 register-blocked f32x2 GEMM layers.
// ---------------------------------------------------------------------------

#define RES   512
#define EMB   32
#define HID   128
#define TILE  64
#define NTHR  256
#define GRID_FUSED 456

// 3*512*512*32 floats = 96 MB scratch (static device global: allowed)
__device__ __align__(16) float g_planesT[3 * RES * RES * EMB];

// ---------------- packed f32x2 helpers -------------------------------------
typedef unsigned long long u64;

__device__ __forceinline__ u64 fma2(u64 a, u64 b, u64 c) {
    u64 d;
    asm("fma.rn.f32x2 %0, %1, %2, %3;" : "=l"(d) : "l"(a), "l"(b), "l"(c));
    return d;
}
__device__ __forceinline__ u64 dup2(float a) {
    u64 d;
    asm("mov.b64 %0, {%1, %1};" : "=l"(d) : "f"(a));
    return d;
}
__device__ __forceinline__ u64 pack2f(float x, float y) {
    u64 d;
    asm("mov.b64 %0, {%1, %2};" : "=l"(d) : "f"(x), "f"(y));
    return d;
}
__device__ __forceinline__ float2 unpack2(u64 a) {
    float2 r;
    asm("mov.b64 {%0, %1}, %2;" : "=f"(r.x), "=f"(r.y) : "l"(a));
    return r;
}

// ---------------- transpose planes -----------------------------------------
// planes [p][c][y][x] -> g_planesT [p][y][x][c]; 32c x 32x tiles via smem.
__global__ void transpose_planes_kernel(const float* __restrict__ planes) {
    __shared__ float s[32][33];
    int b  = blockIdx.x;               // 3 * 512 * 16 blocks
    int xb = b & 15;
    int y  = (b >> 4) & 511;
    int p  = b >> 13;
    int t  = threadIdx.x;
#pragma unroll
    for (int r = 0; r < 4; r++) {
        int e = t + r * 256;
        int c = e >> 5;
        int x = e & 31;
        size_t src = ((((size_t)p * 32 + c) * RES + y) << 9) + (xb << 5) + x;
        s[c][x] = planes[src];
    }
    __syncthreads();
#pragma unroll
    for (int r = 0; r < 4; r++) {
        int e = t + r * 256;
        int x = e >> 5;
        int c = e & 31;
        size_t dst = (((size_t)p * RES + y) * RES + (xb << 5) + x) * EMB + c;
        g_planesT[dst] = s[c][x];
    }
}

// ---------------- smem layout (floats) -------------------------------------
//  w0s   [32][128]   4096   @ 0
//  w1s   [128][128] 16384   @ 4096
//  w2s   [128][128] 16384   @ 20480
//  feats [64][36]    2304   @ 36864
//  hA    [128][64]   8192   @ 39168
//  hB    [128][64]   8192   @ 47360
//  mi    int [3][64]  192   @ 55552
//  mw    f2  [3][64]  384   @ 55744
//  b0s   [128]        128   @ 56128
//  b1s   [128]        128   @ 56256
//  b2s   [128]        128   @ 56384
//  w3s   [128]        128   @ 56512
//  b3s   [4]            4   @ 56640
// total 56644 floats = 226576 bytes
#define OFF_W0    0
#define OFF_W1    4096
#define OFF_W2    20480
#define OFF_FEATS 36864
#define OFF_HA    39168
#define OFF_HB    47360
#define OFF_MI    55552
#define OFF_MW    55744
#define OFF_B0    56128
#define OFF_B1    56256
#define OFF_B2    56384
#define OFF_W3    56512
#define OFF_B3    56640
#define SMEM_FLOATS 56644

// One layer: out[j][pt] = relu(bias[j] + sum_k in[k]*wT[k][j])
// Each thread: 2 points (ptA = t&31, ptB = ptA+32), 16 j's (8 f32x2 pairs).
// inAct addressed as inAct[k*sk + pt*sp]. out stride TILE (=64) per j.
__device__ __forceinline__ void mlp_layer(const float* __restrict__ inAct,
                                          float* __restrict__ outAct,
                                          const float* __restrict__ wbuf,
                                          const float* __restrict__ bias,
                                          int K, int sk, int sp, int t) {
    int ptA = t & 31;
    int ptB = ptA + 32;
    int j0  = (t >> 5) << 4;   // 0,16,...,112 (uniform within a warp)

    u64 acc0[8], acc1[8];
#pragma unroll
    for (int i = 0; i < 8; i++) {
        u64 bb = pack2f(bias[j0 + 2 * i], bias[j0 + 2 * i + 1]);
        acc0[i] = bb;
        acc1[i] = bb;
    }

#pragma unroll 4
    for (int k = 0; k < K; k++) {
        float aA = inAct[k * sk + ptA * sp];
        float aB = inAct[k * sk + ptB * sp];
        u64 dA = dup2(aA);
        u64 dB = dup2(aB);
        const ulonglong2* wp = (const ulonglong2*)(wbuf + (k << 7) + j0);
#pragma unroll
        for (int i = 0; i < 4; i++) {
            ulonglong2 wv = wp[i];
            acc0[2 * i]     = fma2(wv.x, dA, acc0[2 * i]);
            acc0[2 * i + 1] = fma2(wv.y, dA, acc0[2 * i + 1]);
            acc1[2 * i]     = fma2(wv.x, dB, acc1[2 * i]);
            acc1[2 * i + 1] = fma2(wv.y, dB, acc1[2 * i + 1]);
        }
    }

#pragma unroll
    for (int i = 0; i < 8; i++) {
        float2 vA = unpack2(acc0[i]);
        float2 vB = unpack2(acc1[i]);
        int j = j0 + 2 * i;
        outAct[j * TILE + ptA]       = fmaxf(vA.x, 0.0f);
        outAct[j * TILE + ptB]       = fmaxf(vB.x, 0.0f);
        outAct[(j + 1) * TILE + ptA] = fmaxf(vA.y, 0.0f);
        outAct[(j + 1) * TILE + ptB] = fmaxf(vB.y, 0.0f);
    }
}

__global__ void __launch_bounds__(NTHR, 1)
fused_kernel(const float* __restrict__ coords,
             const float* __restrict__ w0, const float* __restrict__ b0,
             const float* __restrict__ w1, const float* __restrict__ b1,
             const float* __restrict__ w2, const float* __restrict__ b2,
             const float* __restrict__ w3, const float* __restrict__ b3,
             float* __restrict__ out, int N) {
    extern __shared__ float sm[];
    float*  w0s   = sm + OFF_W0;
    float*  w1s   = sm + OFF_W1;
    float*  w2s   = sm + OFF_W2;
    float*  feats = sm + OFF_FEATS;
    float*  hA    = sm + OFF_HA;
    float*  hB    = sm + OFF_HB;
    int*    mi    = (int*)(sm + OFF_MI);
    float2* mw    = (float2*)(sm + OFF_MW);

    int t = threadIdx.x;

    // ---- one-time per block: transpose weights + biases into smem ----
    for (int i = t; i < EMB * HID; i += NTHR) {        // w0 [j][k] -> [k][j]
        int j = i >> 5, k = i & 31;
        w0s[k * HID + j] = __ldg(w0 + i);
    }
    for (int i = t; i < HID * HID; i += NTHR) {        // w1,w2 [j][k] -> [k][j]
        int j = i >> 7, k = i & 127;
        float v1 = __ldg(w1 + i);
        float v2 = __ldg(w2 + i);
        w1s[k * HID + j] = v1;
        w2s[k * HID + j] = v2;
    }
    if (t < HID) {
        sm[OFF_B0 + t] = __ldg(b0 + t);
        sm[OFF_B1 + t] = __ldg(b1 + t);
        sm[OFF_B2 + t] = __ldg(b2 + t);
        sm[OFF_W3 + t] = __ldg(w3 + t);
    }
    if (t == 0) sm[OFF_B3] = __ldg(b3);
    __syncthreads();

    int numTiles = (N + TILE - 1) / TILE;
    for (int tile = blockIdx.x; tile < numTiles; tile += gridDim.x) {
        int base = tile * TILE;

        // ---- Phase A: per-point coords -> (ix0,iy0,wx1,wy1) per plane ----
        if (t < TILE) {
            int g = base + t;
            bool ok = g < N;
            float cx = 0.f, cy = 0.f, cz = 0.f;
            if (ok) {
                cx = coords[3 * g + 0];
                cy = coords[3 * g + 1];
                cz = coords[3 * g + 2];
            }
#pragma unroll
            for (int p = 0; p < 3; p++) {
                float sx = (p == 0) ? cx : ((p == 1) ? cy : cx);
                float sy = (p == 0) ? cy : ((p == 1) ? cz : cz);
                int ix0, iy0; float wx1, wy1;
                if (ok) {
                    float x = (sx + 1.0f) * 0.5f * (float)(RES - 1);
                    float y = (sy + 1.0f) * 0.5f * (float)(RES - 1);
                    float fx = floorf(x), fy = floorf(y);
                    ix0 = (int)fx; iy0 = (int)fy;
                    wx1 = x - fx;  wy1 = y - fy;
                } else {
                    ix0 = 2000; iy0 = 2000; wx1 = 0.f; wy1 = 0.f;
                }
                mi[p * TILE + t] = (iy0 << 16) | (ix0 & 0xFFFF);
                mw[p * TILE + t] = make_float2(wx1, wy1);
            }
        }
        __syncthreads();

        // ---- Phase B: cooperative gather. 8 lanes per texel line ----
        {
            int w    = t >> 5;
            int lane = t & 31;
            int g4   = lane >> 3;   // 4 points in flight per warp pass
            int sub  = lane & 7;    // float4 slot within 128B texel line
#pragma unroll
            for (int r = 0; r < 2; r++) {
                int pt = w * 8 + r * 4 + g4;
                float4 acc = make_float4(0.f, 0.f, 0.f, 0.f);
#pragma unroll
                for (int p = 0; p < 3; p++) {
                    int m = mi[p * TILE + pt];
                    int ix0 = (int)(short)(m & 0xFFFF);
                    int iy0 = m >> 16;
                    float2 wf = mw[p * TILE + pt];
                    float wx1 = wf.x, wy1 = wf.y;
                    float wx0 = 1.0f - wx1, wy0 = 1.0f - wy1;
#pragma unroll
                    for (int c = 0; c < 4; c++) {
                        int ix = ix0 + (c & 1);
                        int iy = iy0 + (c >> 1);
                        float wgt = ((c & 1) ? wx1 : wx0) * ((c >> 1) ? wy1 : wy0);
                        if ((unsigned)ix < (unsigned)RES && (unsigned)iy < (unsigned)RES) {
                            const float4* ptr =
                                (const float4*)(g_planesT +
                                    ((((size_t)p * RES + iy) * RES + ix) << 5)) + sub;
                            float4 v = __ldg(ptr);
                            acc.x = fmaf(wgt, v.x, acc.x);
                            acc.y = fmaf(wgt, v.y, acc.y);
                            acc.z = fmaf(wgt, v.z, acc.z);
                            acc.w = fmaf(wgt, v.w, acc.w);
                        }
                    }
                }
                *(float4*)(feats + pt * 36 + sub * 4) = acc;
            }
        }
        __syncthreads();

        // ---- MLP (weights already resident) ----
        mlp_layer(feats, hA, w0s, sm + OFF_B0, EMB, 1, 36, t);
        __syncthreads();
        mlp_layer(hA, hB, w1s, sm + OFF_B1, HID, TILE, 1, t);
        __syncthreads();
        mlp_layer(hB, hA, w2s, sm + OFF_B2, HID, TILE, 1, t);
        __syncthreads();

        // ---- output layer: out[pt] = b3 + sum_k hA[k][pt] * w3[k] ----
        if (t < TILE) {
            int g = base + t;
            float acc = sm[OFF_B3];
            const float* w3p = sm + OFF_W3;
#pragma unroll 8
            for (int k = 0; k < HID; k++)
                acc = fmaf(hA[k * TILE + t], w3p[k], acc);
            if (g < N) out[g] = acc;
        }
        __syncthreads();
    }
}

// ---------------------------------------------------------------------------
extern "C" void kernel_launch(void* const* d_in, const int* in_sizes, int n_in,
                              void* d_out, int out_size) {
    const float* coords = (const float*)d_in[0];
    const float* planes = (const float*)d_in[1];
    const float* w0     = (const float*)d_in[2];
    const float* b0     = (const float*)d_in[3];
    const float* w1     = (const float*)d_in[4];
    const float* b1     = (const float*)d_in[5];
    const float* w2     = (const float*)d_in[6];
    const float* b2     = (const float*)d_in[7];
    const float* w3     = (const float*)d_in[8];
    const float* b3     = (const float*)d_in[9];
    float* out = (float*)d_out;

    int N = in_sizes[0] / 3;

    static const int smem_bytes = SMEM_FLOATS * 4;
    cudaFuncSetAttribute(fused_kernel,
                         cudaFuncAttributeMaxDynamicSharedMemorySize,
                         smem_bytes);

    transpose_planes_kernel<<<3 * RES * (RES / 32), 256>>>(planes);
    fused_kernel<<<GRID_FUSED, NTHR, smem_bytes>>>(coords, w0, b0, w1, b1,
                                                   w2, b2, w3, b3, out, N);
}

// round 7
// speedup vs baseline: 1.5848x; 1.3449x over previous
#include <cuda_runtime.h>
#include <cuda_bf16.h>
#include <cstdint>
#include <cstddef>

// ---------------------------------------------------------------------------
// Net_3813930959289 round 6 (round-5 resubmit after infra flake, + x4 B loads)
// Triplane gather + MLP via mma.sync (HMMA bf16, fp32 accum).
//  - planes transposed channel-last once (96MB device scratch)
//  - persistent fused kernel: 148 blocks x 256 thr; each WARP independently
//    processes 16-point tiles (no __syncthreads in main loop).
//  - weights split bf16 hi/lo, block-resident in smem (swizzled for ldmatrix)
//  - activations bf16 hi/lo in warp-private smem rows
//  - each layer: D = Ah*Wh + Ah*Wl + Al*Wh   (fp32 accumulators in registers)
// ---------------------------------------------------------------------------

#define RES 512
#define EMB 32
#define HID 128
#define NTHR 256
#define GRID_FUSED 148

__device__ __align__(16) float g_planesT[3 * RES * RES * EMB];

// ---- smem byte offsets ------------------------------------------------------
#define OFF_WH0   0        // [128 j][32 k] bf16, stride 64B, swz ^(j&3)
#define OFF_WL0   8192
#define OFF_WH1   16384    // [128][128] bf16, stride 256B, swz ^(j&7)
#define OFF_WL1   49152
#define OFF_WH2   81920
#define OFF_WL2   114688
#define OFF_ACTH  147456   // 8 warps x [16 rows][256B] bf16, swz ^(r&7)
#define OFF_ACTL  180224
#define OFF_B0    212992
#define OFF_B1    213504
#define OFF_B2    214016
#define OFF_W3    214528
#define OFF_B3    215040
#define SMEM_BYTES 215056

// ---------------- asm helpers ------------------------------------------------
__device__ __forceinline__ uint32_t smem_u32(const void* p) {
    uint32_t a;
    asm("{ .reg .u64 t; cvta.to.shared.u64 t, %1; cvt.u32.u64 %0, t; }"
        : "=r"(a) : "l"(p));
    return a;
}
__device__ __forceinline__ void ldsm_x4(uint32_t r[4], uint32_t addr) {
    asm volatile("ldmatrix.sync.aligned.m8n8.x4.shared.b16 {%0,%1,%2,%3}, [%4];"
        : "=r"(r[0]), "=r"(r[1]), "=r"(r[2]), "=r"(r[3]) : "r"(addr));
}
__device__ __forceinline__ void st32(uint32_t addr, uint32_t v) {
    asm volatile("st.shared.b32 [%0], %1;" :: "r"(addr), "r"(v));
}
__device__ __forceinline__ void mma2(float (&d)[4], const uint32_t (&a)[4],
                                     uint32_t b0, uint32_t b1) {
    asm volatile(
        "mma.sync.aligned.m16n8k16.row.col.f32.bf16.bf16.f32 "
        "{%0,%1,%2,%3}, {%4,%5,%6,%7}, {%8,%9}, {%0,%1,%2,%3};"
        : "+f"(d[0]), "+f"(d[1]), "+f"(d[2]), "+f"(d[3])
        : "r"(a[0]), "r"(a[1]), "r"(a[2]), "r"(a[3]), "r"(b0), "r"(b1));
}
// pack two fp32 -> bf16x2 (lo arg in low half)
__device__ __forceinline__ uint32_t packbf(float lo, float hi) {
    uint32_t r;
    asm("cvt.rn.bf16x2.f32 %0, %1, %2;" : "=r"(r) : "f"(hi), "f"(lo));
    return r;
}
__device__ __forceinline__ float bfr(float v) {
    return __bfloat162float(__float2bfloat16(v));
}

// ---------------- transpose planes ------------------------------------------
__global__ void transpose_planes_kernel(const float* __restrict__ planes) {
    __shared__ float s[32][33];
    int b  = blockIdx.x;
    int xb = b & 15;
    int y  = (b >> 4) & 511;
    int p  = b >> 13;
    int t  = threadIdx.x;
#pragma unroll
    for (int r = 0; r < 4; r++) {
        int e = t + r * 256;
        int c = e >> 5;
        int x = e & 31;
        size_t src = ((((size_t)p * 32 + c) * RES + y) << 9) + (xb << 5) + x;
        s[c][x] = planes[src];
    }
    __syncthreads();
#pragma unroll
    for (int r = 0; r < 4; r++) {
        int e = t + r * 256;
        int x = e >> 5;
        int c = e & 31;
        size_t dst = (((size_t)p * RES + y) * RES + (xb << 5) + x) * EMB + c;
        g_planesT[dst] = s[c][x];
    }
}

// ---------------- per-layer GEMM (warp-level) -------------------------------
// D[16 rows][128 j] += A[16][K] * W[j][K]^T ; acc must be bias-initialized.
// B loaded as ldmatrix.x4: tiles {n0-7/k-lo, n0-7/k-hi, n8-15/k-lo, n8-15/k-hi}
template<int KC, int WSTRIDE, int WMASK>
__device__ __forceinline__ void run_layer(float (&acc)[16][4],
                                          uint32_t aH, uint32_t aL,
                                          uint32_t wHb, uint32_t wLb,
                                          int lane) {
    int rowoff = lane & 7;
    int arow   = rowoff + ((lane >> 3) & 1) * 8;  // A x4 lane->row mapping
    int kpA    = (lane >> 4) & 1;
    int brow   = rowoff + ((lane >> 4) & 1) * 8;  // B x4: tiles 2,3 = rows+8
    int bmB    = (lane >> 3) & 1;                 // B x4: tiles 1,3 = k-hi
    uint32_t aRowH = aH + (uint32_t)arow * 256u;
    uint32_t aRowL = aL + (uint32_t)arow * 256u;
    uint32_t bRowH = wHb + (uint32_t)brow * WSTRIDE;
    uint32_t bRowL = wLb + (uint32_t)brow * WSTRIDE;
#pragma unroll
    for (int kc = 0; kc < KC; kc++) {
        uint32_t ah[4], al[4];
        uint32_t aoff = (uint32_t)((2 * kc + kpA) ^ rowoff) << 4;
        ldsm_x4(ah, aRowH + aoff);
        ldsm_x4(al, aRowL + aoff);
        uint32_t boff = (uint32_t)((2 * kc + bmB) ^ (rowoff & WMASK)) << 4;
#pragma unroll
        for (int np = 0; np < 8; np++) {
            uint32_t bh[4], bl[4];
            uint32_t nb = (uint32_t)(np * 16 * WSTRIDE) + boff;
            ldsm_x4(bh, bRowH + nb);
            ldsm_x4(bl, bRowL + nb);
            mma2(acc[2 * np],     ah, bh[0], bh[1]);
            mma2(acc[2 * np + 1], ah, bh[2], bh[3]);
            mma2(acc[2 * np],     ah, bl[0], bl[1]);
            mma2(acc[2 * np + 1], ah, bl[2], bl[3]);
            mma2(acc[2 * np],     al, bh[0], bh[1]);
            mma2(acc[2 * np + 1], al, bh[2], bh[3]);
        }
    }
}

__device__ __forceinline__ void acc_init(float (&acc)[16][4],
                                         const float* __restrict__ bias,
                                         int lane) {
    int t2 = (lane & 3) * 2;
#pragma unroll
    for (int n = 0; n < 16; n++) {
        float2 bv = *(const float2*)(bias + n * 8 + t2);
        acc[n][0] = bv.x; acc[n][1] = bv.y;
        acc[n][2] = bv.x; acc[n][3] = bv.y;
    }
}

// relu + bf16 hi/lo split + store to warp act rows
__device__ __forceinline__ void epi(float (&acc)[16][4],
                                    uint32_t aH, uint32_t aL, int lane) {
    int g = lane >> 2, t = lane & 3;
    uint32_t rowA = (uint32_t)g * 256u + (uint32_t)t * 4u;
    uint32_t rowB = (uint32_t)(g + 8) * 256u + (uint32_t)t * 4u;
#pragma unroll
    for (int n = 0; n < 16; n++) {
        float v0 = fmaxf(acc[n][0], 0.f), v1 = fmaxf(acc[n][1], 0.f);
        float v2 = fmaxf(acc[n][2], 0.f), v3 = fmaxf(acc[n][3], 0.f);
        uint32_t swz = (uint32_t)(n ^ g) << 4;
        st32(aH + rowA + swz, packbf(v0, v1));
        st32(aL + rowA + swz, packbf(v0 - bfr(v0), v1 - bfr(v1)));
        st32(aH + rowB + swz, packbf(v2, v3));
        st32(aL + rowB + swz, packbf(v2 - bfr(v2), v3 - bfr(v3)));
    }
}

// ---------------- fused kernel ----------------------------------------------
__global__ void __launch_bounds__(NTHR, 1)
fused_kernel(const float* __restrict__ coords,
             const float* __restrict__ w0, const float* __restrict__ b0,
             const float* __restrict__ w1, const float* __restrict__ b1,
             const float* __restrict__ w2, const float* __restrict__ b2,
             const float* __restrict__ w3, const float* __restrict__ b3,
             float* __restrict__ out, int N) {
    extern __shared__ char sm[];
    uint32_t smb = smem_u32(sm);
    int t    = threadIdx.x;
    int wid  = t >> 5;
    int lane = t & 31;

    // ---- one-time: split weights to bf16 hi/lo, swizzled for ldmatrix ----
    for (int i = t; i < HID * EMB; i += NTHR) {     // w0 [j][32]
        int j = i >> 5, k = i & 31;
        float v = __ldg(w0 + i);
        float h = bfr(v);
        uint32_t off = (uint32_t)j * 64u + (uint32_t)(((k >> 3) ^ (j & 3)) << 4)
                       + (uint32_t)((k & 7) * 2);
        *(__nv_bfloat16*)(sm + OFF_WH0 + off) = __float2bfloat16(v);
        *(__nv_bfloat16*)(sm + OFF_WL0 + off) = __float2bfloat16(v - h);
    }
    for (int i = t; i < HID * HID; i += NTHR) {     // w1, w2 [j][128]
        int j = i >> 7, k = i & 127;
        uint32_t off = (uint32_t)j * 256u + (uint32_t)(((k >> 3) ^ (j & 7)) << 4)
                       + (uint32_t)((k & 7) * 2);
        float v1 = __ldg(w1 + i);
        float h1 = bfr(v1);
        *(__nv_bfloat16*)(sm + OFF_WH1 + off) = __float2bfloat16(v1);
        *(__nv_bfloat16*)(sm + OFF_WL1 + off) = __float2bfloat16(v1 - h1);
        float v2 = __ldg(w2 + i);
        float h2 = bfr(v2);
        *(__nv_bfloat16*)(sm + OFF_WH2 + off) = __float2bfloat16(v2);
        *(__nv_bfloat16*)(sm + OFF_WL2 + off) = __float2bfloat16(v2 - h2);
    }
    if (t < HID) {
        ((float*)(sm + OFF_B0))[t] = __ldg(b0 + t);
        ((float*)(sm + OFF_B1))[t] = __ldg(b1 + t);
        ((float*)(sm + OFF_B2))[t] = __ldg(b2 + t);
        ((float*)(sm + OFF_W3))[t] = __ldg(w3 + t);
    }
    if (t == 0) *(float*)(sm + OFF_B3) = __ldg(b3);
    __syncthreads();

    const float* b0s = (const float*)(sm + OFF_B0);
    const float* b1s = (const float*)(sm + OFF_B1);
    const float* b2s = (const float*)(sm + OFF_B2);
    const float* w3s = (const float*)(sm + OFF_W3);
    const float  b3v = *(const float*)(sm + OFF_B3);

    uint32_t actH = smb + OFF_ACTH + (uint32_t)wid * 4096u;  // 16 rows x 256B
    uint32_t actL = smb + OFF_ACTL + (uint32_t)wid * 4096u;
    uint32_t wh0 = smb + OFF_WH0, wl0 = smb + OFF_WL0;
    uint32_t wh1 = smb + OFF_WH1, wl1 = smb + OFF_WL1;
    uint32_t wh2 = smb + OFF_WH2, wl2 = smb + OFF_WL2;

    int gwarp  = blockIdx.x * 8 + wid;
    int stride = gridDim.x * 8;
    int numT   = (N + 15) >> 4;

    int g4 = lane >> 3, sub = lane & 7;

    for (int tile = gwarp; tile < numT; tile += stride) {
        int base = tile << 4;

        // ---- Phase A: lanes 0..15 compute per-point texel data ----
        int   mm[3];
        float wxv[3], wyv[3];
        {
            int pt = base + lane;
            bool ok = (lane < 16) && (pt < N);
            float cx = 0.f, cy = 0.f, cz = 0.f;
            if (ok) {
                cx = coords[3 * pt + 0];
                cy = coords[3 * pt + 1];
                cz = coords[3 * pt + 2];
            }
#pragma unroll
            for (int p = 0; p < 3; p++) {
                float sx = (p == 0) ? cx : ((p == 1) ? cy : cx);
                float sy = (p == 0) ? cy : ((p == 1) ? cz : cz);
                int ix0 = 4000, iy0 = 4000;
                float wx1 = 0.f, wy1 = 0.f;
                if (ok) {
                    float x = (sx + 1.0f) * 0.5f * (float)(RES - 1);
                    float y = (sy + 1.0f) * 0.5f * (float)(RES - 1);
                    float fx = floorf(x), fy = floorf(y);
                    ix0 = (int)fx; iy0 = (int)fy;
                    wx1 = x - fx;  wy1 = y - fy;
                }
                mm[p]  = (iy0 << 16) | (ix0 & 0xFFFF);
                wxv[p] = wx1;
                wyv[p] = wy1;
            }
        }

        // ---- Phase B: gather, 8 lanes per point, 4 points per pass ----
        __syncwarp();
#pragma unroll
        for (int r = 0; r < 4; r++) {
            int src = r * 4 + g4;       // local point 0..15
            float4 a4 = make_float4(0.f, 0.f, 0.f, 0.f);
#pragma unroll
            for (int p = 0; p < 3; p++) {
                int   m   = __shfl_sync(0xffffffffu, mm[p],  src);
                float wx1 = __shfl_sync(0xffffffffu, wxv[p], src);
                float wy1 = __shfl_sync(0xffffffffu, wyv[p], src);
                int ix0 = (int)(short)(m & 0xFFFF);
                int iy0 = m >> 16;
                float wx0 = 1.0f - wx1, wy0 = 1.0f - wy1;
#pragma unroll
                for (int c = 0; c < 4; c++) {
                    int ix = ix0 + (c & 1);
                    int iy = iy0 + (c >> 1);
                    float wgt = ((c & 1) ? wx1 : wx0) * ((c >> 1) ? wy1 : wy0);
                    if ((unsigned)ix < (unsigned)RES && (unsigned)iy < (unsigned)RES) {
                        const float4* ptr =
                            (const float4*)(g_planesT +
                                ((((size_t)p * RES + iy) * RES + ix) << 5)) + sub;
                        float4 v = __ldg(ptr);
                        a4.x = fmaf(wgt, v.x, a4.x);
                        a4.y = fmaf(wgt, v.y, a4.y);
                        a4.z = fmaf(wgt, v.z, a4.z);
                        a4.w = fmaf(wgt, v.w, a4.w);
                    }
                }
            }
            // store k = sub*4 .. sub*4+3 of row (r*4+g4), bf16 hi/lo
            int row = r * 4 + g4;
            uint32_t off = (uint32_t)row * 256u
                         + (uint32_t)(((sub >> 1) ^ (row & 7)) << 4)
                         + (uint32_t)((sub & 1) << 3);
            st32(actH + off,     packbf(a4.x, a4.y));
            st32(actH + off + 4, packbf(a4.z, a4.w));
            st32(actL + off,     packbf(a4.x - bfr(a4.x), a4.y - bfr(a4.y)));
            st32(actL + off + 4, packbf(a4.z - bfr(a4.z), a4.w - bfr(a4.w)));
        }
        __syncwarp();

        float acc[16][4];

        // ---- layer 1: K=32 ----
        acc_init(acc, b0s, lane);
        run_layer<2, 64, 3>(acc, actH, actL, wh0, wl0, lane);
        epi(acc, actH, actL, lane);
        __syncwarp();

        // ---- layer 2: K=128 ----
        acc_init(acc, b1s, lane);
        run_layer<8, 256, 7>(acc, actH, actL, wh1, wl1, lane);
        epi(acc, actH, actL, lane);
        __syncwarp();

        // ---- layer 3: K=128, fused output dot ----
        acc_init(acc, b2s, lane);
        run_layer<8, 256, 7>(acc, actH, actL, wh2, wl2, lane);
        {
            float s0 = 0.f, s1 = 0.f;
            int t2 = (lane & 3) * 2;
#pragma unroll
            for (int n = 0; n < 16; n++) {
                float2 wv = *(const float2*)(w3s + n * 8 + t2);
                s0 += fmaxf(acc[n][0], 0.f) * wv.x + fmaxf(acc[n][1], 0.f) * wv.y;
                s1 += fmaxf(acc[n][2], 0.f) * wv.x + fmaxf(acc[n][3], 0.f) * wv.y;
            }
            s0 += __shfl_xor_sync(0xffffffffu, s0, 1);
            s0 += __shfl_xor_sync(0xffffffffu, s0, 2);
            s1 += __shfl_xor_sync(0xffffffffu, s1, 1);
            s1 += __shfl_xor_sync(0xffffffffu, s1, 2);
            if ((lane & 3) == 0) {
                int g = lane >> 2;
                int p0 = base + g, p1 = base + g + 8;
                if (p0 < N) out[p0] = s0 + b3v;
                if (p1 < N) out[p1] = s1 + b3v;
            }
        }
        __syncwarp();
    }
}

// ---------------------------------------------------------------------------
extern "C" void kernel_launch(void* const* d_in, const int* in_sizes, int n_in,
                              void* d_out, int out_size) {
    const float* coords = (const float*)d_in[0];
    const float* planes = (const float*)d_in[1];
    const float* w0     = (const float*)d_in[2];
    const float* b0     = (const float*)d_in[3];
    const float* w1     = (const float*)d_in[4];
    const float* b1     = (const float*)d_in[5];
    const float* w2     = (const float*)d_in[6];
    const float* b2     = (const float*)d_in[7];
    const float* w3     = (const float*)d_in[8];
    const float* b3     = (const float*)d_in[9];
    float* out = (float*)d_out;

    int N = in_sizes[0] / 3;

    cudaFuncSetAttribute(fused_kernel,
                         cudaFuncAttributeMaxDynamicSharedMemorySize,
                         SMEM_BYTES);

    transpose_planes_kernel<<<3 * RES * (RES / 32), 256>>>(planes);
    fused_kernel<<<GRID_FUSED, NTHR, SMEM_BYTES>>>(coords, w0, b0, w1, b1,
                                                   w2, b2, w3, b3, out, N);
}

// round 11
// speedup vs baseline: 3.0182x; 1.9045x over previous
#include <cuda_runtime.h>
#include <cuda_bf16.h>
#include <cstdint>
#include <cstddef>

// ---------------------------------------------------------------------------
// Net_3813930959289 round 8: warp-PAIR cooperative HMMA MLP.
//  - 512 threads (16 warps) per block, 148 persistent blocks.
//  - each warp pair owns a 16-point tile: warp computes N=64 of 128 outputs
//    (acc 8x4 = 32 regs -> fits 128-reg budget at 512 thr, 4 warps/SMSP).
//  - pair sync via named barriers; no block barrier in main loop.
//  - weights bf16 hi/lo resident in smem; 3-term split MMA (Ah*Wh+Ah*Wl+Al*Wh)
// ---------------------------------------------------------------------------

#define RES 512
#define EMB 32
#define HID 128
#define NTHR 512
#define GRID_FUSED 148

__device__ __align__(16) float g_planesT[3 * RES * RES * EMB];

// ---- smem byte offsets ------------------------------------------------------
#define OFF_WH0   0        // [128 j][32 k] bf16, stride 64B, swz ^(j&3)
#define OFF_WL0   8192
#define OFF_WH1   16384    // [128][128] bf16, stride 256B, swz ^(j&7)
#define OFF_WL1   49152
#define OFF_WH2   81920
#define OFF_WL2   114688
#define OFF_ACTH  147456   // 8 pairs x [16 rows][256B] bf16, swz ^(r&7)
#define OFF_ACTL  180224
#define OFF_B0    212992
#define OFF_B1    213504
#define OFF_B2    214016
#define OFF_W3    214528
#define OFF_B3    215040
#define OFF_PART  215056   // 8 pairs x 32 floats (pair partial dots)
#define SMEM_BYTES 216080

// ---------------- asm helpers ------------------------------------------------
__device__ __forceinline__ uint32_t smem_u32(const void* p) {
    uint32_t a;
    asm("{ .reg .u64 t; cvta.to.shared.u64 t, %1; cvt.u32.u64 %0, t; }"
        : "=r"(a) : "l"(p));
    return a;
}
__device__ __forceinline__ void ldsm_x4(uint32_t r[4], uint32_t addr) {
    asm volatile("ldmatrix.sync.aligned.m8n8.x4.shared.b16 {%0,%1,%2,%3}, [%4];"
        : "=r"(r[0]), "=r"(r[1]), "=r"(r[2]), "=r"(r[3]) : "r"(addr));
}
__device__ __forceinline__ void st32(uint32_t addr, uint32_t v) {
    asm volatile("st.shared.b32 [%0], %1;" :: "r"(addr), "r"(v));
}
__device__ __forceinline__ void mma2(float (&d)[4], const uint32_t (&a)[4],
                                     uint32_t b0, uint32_t b1) {
    asm volatile(
        "mma.sync.aligned.m16n8k16.row.col.f32.bf16.bf16.f32 "
        "{%0,%1,%2,%3}, {%4,%5,%6,%7}, {%8,%9}, {%0,%1,%2,%3};"
        : "+f"(d[0]), "+f"(d[1]), "+f"(d[2]), "+f"(d[3])
        : "r"(a[0]), "r"(a[1]), "r"(a[2]), "r"(a[3]), "r"(b0), "r"(b1));
}
__device__ __forceinline__ uint32_t packbf(float lo, float hi) {
    uint32_t r;
    asm("cvt.rn.bf16x2.f32 %0, %1, %2;" : "=r"(r) : "f"(hi), "f"(lo));
    return r;
}
__device__ __forceinline__ float bfr(float v) {
    return __bfloat162float(__float2bfloat16(v));
}
__device__ __forceinline__ void bar_pair(int pair) {
    asm volatile("bar.sync %0, 64;" :: "r"(pair + 1) : "memory");
}

// ---------------- transpose planes ------------------------------------------
__global__ void transpose_planes_kernel(const float* __restrict__ planes) {
    __shared__ float s[32][33];
    int b  = blockIdx.x;
    int xb = b & 15;
    int y  = (b >> 4) & 511;
    int p  = b >> 13;
    int t  = threadIdx.x;
#pragma unroll
    for (int r = 0; r < 4; r++) {
        int e = t + r * 256;
        int c = e >> 5;
        int x = e & 31;
        size_t src = ((((size_t)p * 32 + c) * RES + y) << 9) + (xb << 5) + x;
        s[c][x] = planes[src];
    }
    __syncthreads();
#pragma unroll
    for (int r = 0; r < 4; r++) {
        int e = t + r * 256;
        int x = e >> 5;
        int c = e & 31;
        size_t dst = (((size_t)p * RES + y) * RES + (xb << 5) + x) * EMB + c;
        g_planesT[dst] = s[c][x];
    }
}

// ---------------- per-layer GEMM (warp computes N=64 slice) -----------------
// acc[8][4]: D rows 0..15 x j = nbase + np*16 + {0..15}
template<int KC, int WSTRIDE, int WMASK>
__device__ __forceinline__ void run_layer(float (&acc)[8][4],
                                          uint32_t aH, uint32_t aL,
                                          uint32_t wHb, uint32_t wLb,
                                          int lane) {
    int rowoff = lane & 7;
    int arow   = rowoff + ((lane >> 3) & 1) * 8;  // A x4 lane->row mapping
    int kpA    = (lane >> 4) & 1;
    int brow   = rowoff + ((lane >> 4) & 1) * 8;  // B x4: tiles 2,3 = rows+8
    int bmB    = (lane >> 3) & 1;                 // B x4: tiles 1,3 = k-hi
    uint32_t aRowH = aH + (uint32_t)arow * 256u;
    uint32_t aRowL = aL + (uint32_t)arow * 256u;
    uint32_t bRowH = wHb + (uint32_t)brow * WSTRIDE;
    uint32_t bRowL = wLb + (uint32_t)brow * WSTRIDE;
#pragma unroll
    for (int kc = 0; kc < KC; kc++) {
        uint32_t ah[4], al[4];
        uint32_t aoff = (uint32_t)((2 * kc + kpA) ^ rowoff) << 4;
        ldsm_x4(ah, aRowH + aoff);
        ldsm_x4(al, aRowL + aoff);
        uint32_t boff = (uint32_t)((2 * kc + bmB) ^ (rowoff & WMASK)) << 4;
#pragma unroll
        for (int np = 0; np < 4; np++) {
            uint32_t bh[4], bl[4];
            uint32_t nb = (uint32_t)(np * 16 * WSTRIDE) + boff;
            ldsm_x4(bh, bRowH + nb);
            ldsm_x4(bl, bRowL + nb);
            mma2(acc[2 * np],     ah, bh[0], bh[1]);
            mma2(acc[2 * np + 1], ah, bh[2], bh[3]);
            mma2(acc[2 * np],     ah, bl[0], bl[1]);
            mma2(acc[2 * np + 1], ah, bl[2], bl[3]);
            mma2(acc[2 * np],     al, bh[0], bh[1]);
            mma2(acc[2 * np + 1], al, bh[2], bh[3]);
        }
    }
}

__device__ __forceinline__ void acc_init(float (&acc)[8][4],
                                         const float* __restrict__ bias,
                                         int lane, int nbase) {
    int t2 = (lane & 3) * 2;
#pragma unroll
    for (int n = 0; n < 8; n++) {
        float2 bv = *(const float2*)(bias + nbase + n * 8 + t2);
        acc[n][0] = bv.x; acc[n][1] = bv.y;
        acc[n][2] = bv.x; acc[n][3] = bv.y;
    }
}

// relu + bf16 hi/lo split + store columns [nbase, nbase+64) of act rows
__device__ __forceinline__ void epi(float (&acc)[8][4],
                                    uint32_t aH, uint32_t aL,
                                    int lane, int wsub) {
    int g = lane >> 2, t = lane & 3;
    uint32_t rowA = (uint32_t)g * 256u + (uint32_t)t * 4u;
    uint32_t rowB = (uint32_t)(g + 8) * 256u + (uint32_t)t * 4u;
#pragma unroll
    for (int n = 0; n < 8; n++) {
        float v0 = fmaxf(acc[n][0], 0.f), v1 = fmaxf(acc[n][1], 0.f);
        float v2 = fmaxf(acc[n][2], 0.f), v3 = fmaxf(acc[n][3], 0.f);
        int chunk = n + 8 * wsub;   // 16B chunk index within 256B row
        uint32_t swz = (uint32_t)(chunk ^ g) << 4;
        st32(aH + rowA + swz, packbf(v0, v1));
        st32(aL + rowA + swz, packbf(v0 - bfr(v0), v1 - bfr(v1)));
        st32(aH + rowB + swz, packbf(v2, v3));
        st32(aL + rowB + swz, packbf(v2 - bfr(v2), v3 - bfr(v3)));
    }
}

// ---------------- fused kernel ----------------------------------------------
__global__ void __launch_bounds__(NTHR, 1)
fused_kernel(const float* __restrict__ coords,
             const float* __restrict__ w0, const float* __restrict__ b0,
             const float* __restrict__ w1, const float* __restrict__ b1,
             const float* __restrict__ w2, const float* __restrict__ b2,
             const float* __restrict__ w3, const float* __restrict__ b3,
             float* __restrict__ out, int N) {
    extern __shared__ char sm[];
    uint32_t smb = smem_u32(sm);
    int t    = threadIdx.x;
    int wid  = t >> 5;
    int lane = t & 31;
    int pair = wid >> 1;
    int wsub = wid & 1;
    int nbase = wsub * 64;

    // ---- one-time: split weights to bf16 hi/lo, swizzled for ldmatrix ----
    for (int i = t; i < HID * EMB; i += NTHR) {     // w0 [j][32]
        int j = i >> 5, k = i & 31;
        float v = __ldg(w0 + i);
        float h = bfr(v);
        uint32_t off = (uint32_t)j * 64u + (uint32_t)(((k >> 3) ^ (j & 3)) << 4)
                       + (uint32_t)((k & 7) * 2);
        *(__nv_bfloat16*)(sm + OFF_WH0 + off) = __float2bfloat16(v);
        *(__nv_bfloat16*)(sm + OFF_WL0 + off) = __float2bfloat16(v - h);
    }
    for (int i = t; i < HID * HID; i += NTHR) {     // w1, w2 [j][128]
        int j = i >> 7, k = i & 127;
        uint32_t off = (uint32_t)j * 256u + (uint32_t)(((k >> 3) ^ (j & 7)) << 4)
                       + (uint32_t)((k & 7) * 2);
        float v1 = __ldg(w1 + i);
        float h1 = bfr(v1);
        *(__nv_bfloat16*)(sm + OFF_WH1 + off) = __float2bfloat16(v1);
        *(__nv_bfloat16*)(sm + OFF_WL1 + off) = __float2bfloat16(v1 - h1);
        float v2 = __ldg(w2 + i);
        float h2 = bfr(v2);
        *(__nv_bfloat16*)(sm + OFF_WH2 + off) = __float2bfloat16(v2);
        *(__nv_bfloat16*)(sm + OFF_WL2 + off) = __float2bfloat16(v2 - h2);
    }
    if (t < HID) {
        ((float*)(sm + OFF_B0))[t] = __ldg(b0 + t);
        ((float*)(sm + OFF_B1))[t] = __ldg(b1 + t);
        ((float*)(sm + OFF_B2))[t] = __ldg(b2 + t);
        ((float*)(sm + OFF_W3))[t] = __ldg(w3 + t);
    }
    if (t == 0) *(float*)(sm + OFF_B3) = __ldg(b3);
    __syncthreads();

    const float* b0s = (const float*)(sm + OFF_B0);
    const float* b1s = (const float*)(sm + OFF_B1);
    const float* b2s = (const float*)(sm + OFF_B2);
    const float* w3s = (const float*)(sm + OFF_W3);
    float* parts     = (float*)(sm + OFF_PART) + pair * 32;
    const float b3v  = *(const float*)(sm + OFF_B3);

    uint32_t actH = smb + OFF_ACTH + (uint32_t)pair * 4096u;  // 16 rows x 256B
    uint32_t actL = smb + OFF_ACTL + (uint32_t)pair * 4096u;
    uint32_t wh0 = smb + OFF_WH0, wl0 = smb + OFF_WL0;
    uint32_t wh1 = smb + OFF_WH1, wl1 = smb + OFF_WL1;
    uint32_t wh2 = smb + OFF_WH2, wl2 = smb + OFF_WL2;

    int gpair  = blockIdx.x * 8 + pair;
    int stride = gridDim.x * 8;
    int numT   = (N + 15) >> 4;

    int g4 = lane >> 3, sub = lane & 7;

    for (int tile = gpair; tile < numT; tile += stride) {
        int base = tile << 4;

        // ---- Phase A: lanes 0..15 compute per-point texel data (both warps)
        int   mm[3];
        float wxv[3], wyv[3];
        {
            int pt = base + lane;
            bool ok = (lane < 16) && (pt < N);
            float cx = 0.f, cy = 0.f, cz = 0.f;
            if (ok) {
                cx = coords[3 * pt + 0];
                cy = coords[3 * pt + 1];
                cz = coords[3 * pt + 2];
            }
#pragma unroll
            for (int p = 0; p < 3; p++) {
                float sx = (p == 0) ? cx : ((p == 1) ? cy : cx);
                float sy = (p == 0) ? cy : ((p == 1) ? cz : cz);
                int ix0 = 4000, iy0 = 4000;
                float wx1 = 0.f, wy1 = 0.f;
                if (ok) {
                    float x = (sx + 1.0f) * 0.5f * (float)(RES - 1);
                    float y = (sy + 1.0f) * 0.5f * (float)(RES - 1);
                    float fx = floorf(x), fy = floorf(y);
                    ix0 = (int)fx; iy0 = (int)fy;
                    wx1 = x - fx;  wy1 = y - fy;
                }
                mm[p]  = (iy0 << 16) | (ix0 & 0xFFFF);
                wxv[p] = wx1;
                wyv[p] = wy1;
            }
        }

        // ---- Phase B: gather. warp a -> points 0..7, warp b -> 8..15 ----
        __syncwarp();
#pragma unroll
        for (int rr = 0; rr < 2; rr++) {
            int r   = 2 * wsub + rr;
            int src = r * 4 + g4;       // local point 0..15
            float4 a4 = make_float4(0.f, 0.f, 0.f, 0.f);
#pragma unroll
            for (int p = 0; p < 3; p++) {
                int   m   = __shfl_sync(0xffffffffu, mm[p],  src);
                float wx1 = __shfl_sync(0xffffffffu, wxv[p], src);
                float wy1 = __shfl_sync(0xffffffffu, wyv[p], src);
                int ix0 = (int)(short)(m & 0xFFFF);
                int iy0 = m >> 16;
                float wx0 = 1.0f - wx1, wy0 = 1.0f - wy1;
#pragma unroll
                for (int c = 0; c < 4; c++) {
                    int ix = ix0 + (c & 1);
                    int iy = iy0 + (c >> 1);
                    float wgt = ((c & 1) ? wx1 : wx0) * ((c >> 1) ? wy1 : wy0);
                    if ((unsigned)ix < (unsigned)RES && (unsigned)iy < (unsigned)RES) {
                        const float4* ptr =
                            (const float4*)(g_planesT +
                                ((((size_t)p * RES + iy) * RES + ix) << 5)) + sub;
                        float4 v = __ldg(ptr);
                        a4.x = fmaf(wgt, v.x, a4.x);
                        a4.y = fmaf(wgt, v.y, a4.y);
                        a4.z = fmaf(wgt, v.z, a4.z);
                        a4.w = fmaf(wgt, v.w, a4.w);
                    }
                }
            }
            int row = r * 4 + g4;
            uint32_t off = (uint32_t)row * 256u
                         + (uint32_t)(((sub >> 1) ^ (row & 7)) << 4)
                         + (uint32_t)((sub & 1) << 3);
            st32(actH + off,     packbf(a4.x, a4.y));
            st32(actH + off + 4, packbf(a4.z, a4.w));
            st32(actL + off,     packbf(a4.x - bfr(a4.x), a4.y - bfr(a4.y)));
            st32(actL + off + 4, packbf(a4.z - bfr(a4.z), a4.w - bfr(a4.w)));
        }
        bar_pair(pair);

        float acc[8][4];

        // ---- layer 1: K=32 ----
        acc_init(acc, b0s, lane, nbase);
        run_layer<2, 64, 3>(acc, actH, actL,
                            wh0 + (uint32_t)nbase * 64u,
                            wl0 + (uint32_t)nbase * 64u, lane);
        bar_pair(pair);                 // epi writes vs other warp's A reads
        epi(acc, actH, actL, lane, wsub);
        bar_pair(pair);

        // ---- layer 2: K=128 ----
        acc_init(acc, b1s, lane, nbase);
        run_layer<8, 256, 7>(acc, actH, actL,
                             wh1 + (uint32_t)nbase * 256u,
                             wl1 + (uint32_t)nbase * 256u, lane);
        bar_pair(pair);
        epi(acc, actH, actL, lane, wsub);
        bar_pair(pair);

        // ---- layer 3: K=128, fused output dot (partial over 64 j's) ----
        acc_init(acc, b2s, lane, nbase);
        run_layer<8, 256, 7>(acc, actH, actL,
                             wh2 + (uint32_t)nbase * 256u,
                             wl2 + (uint32_t)nbase * 256u, lane);
        {
            float s0 = 0.f, s1 = 0.f;
            int t2 = (lane & 3) * 2;
#pragma unroll
            for (int n = 0; n < 8; n++) {
                float2 wv = *(const float2*)(w3s + nbase + n * 8 + t2);
                s0 += fmaxf(acc[n][0], 0.f) * wv.x + fmaxf(acc[n][1], 0.f) * wv.y;
                s1 += fmaxf(acc[n][2], 0.f) * wv.x + fmaxf(acc[n][3], 0.f) * wv.y;
            }
            s0 += __shfl_xor_sync(0xffffffffu, s0, 1);
            s0 += __shfl_xor_sync(0xffffffffu, s0, 2);
            s1 += __shfl_xor_sync(0xffffffffu, s1, 1);
            s1 += __shfl_xor_sync(0xffffffffu, s1, 2);
            if ((lane & 3) == 0) {
                int g = lane >> 2;
                parts[wsub * 16 + g]     = s0;
                parts[wsub * 16 + g + 8] = s1;
            }
        }
        bar_pair(pair);
        if (wsub == 0 && lane < 16) {
            int g = base + lane;
            if (g < N) out[g] = parts[lane] + parts[16 + lane] + b3v;
        }
        bar_pair(pair);   // protect parts + act reuse next tile
    }
}

// ---------------------------------------------------------------------------
extern "C" void kernel_launch(void* const* d_in, const int* in_sizes, int n_in,
                              void* d_out, int out_size) {
    const float* coords = (const float*)d_in[0];
    const float* planes = (const float*)d_in[1];
    const float* w0     = (const float*)d_in[2];
    const float* b0     = (const float*)d_in[3];
    const float* w1     = (const float*)d_in[4];
    const float* b1     = (const float*)d_in[5];
    const float* w2     = (const float*)d_in[6];
    const float* b2     = (const float*)d_in[7];
    const float* w3     = (const float*)d_in[8];
    const float* b3     = (const float*)d_in[9];
    float* out = (float*)d_out;

    int N = in_sizes[0] / 3;

    cudaFuncSetAttribute(fused_kernel,
                         cudaFuncAttributeMaxDynamicSharedMemorySize,
                         SMEM_BYTES);

    transpose_planes_kernel<<<3 * RES * (RES / 32), 256>>>(planes);
    fused_kernel<<<GRID_FUSED, NTHR, SMEM_BYTES>>>(coords, w0, b0, w1, b1,
                                                   w2, b2, w3, b3, out, N);
}